// round 15
// baseline (speedup 1.0000x reference)
#include <cuda_runtime.h>
#include <cstdint>

// L1LossWithPenalty — final grid cell: 256-row tiles x 2 blocks/SM, STAGES=2.
// Same smem (110.6KB) and in-flight bytes as the R11 champion (41.3us), but
// half the tiles (4096) -> half the per-tile sync overhead, and 2 rows per
// consumer thread -> 2x compute per barrier wait.
// out = (1/N) * sum_i [ sum_c |pred[i,c]-tgt[i,c]| ] * penalty[argmax pred_i, argmax tgt_i]
// N = 1048576, C = 27.  226 MB streamed; ~5.6 TB/s sustained = 40.3us floor.

#define C        27
#define ROWS     256                  // rows per tile (2 per consumer thread)
#define CONS     128                  // consumer threads (4 warps)
#define THREADS  160                  // + 1 producer warp
#define TILE_F   (ROWS * C)           // 6912 floats per array
#define TILE_B   (TILE_F * 4)         // 27648 bytes per array per tile
#define STAGE_F  (2 * TILE_F)
#define STAGES   2
#define SMEM_BYTES (STAGES * STAGE_F * 4)   // 110592 B (same as champion)
#define GRID     296

__device__ double   g_acc;
__device__ unsigned g_count;

// ---- mbarrier / TMA-bulk primitives ----
#define MBARRIER_INIT(addr, cnt) \
    asm volatile("mbarrier.init.shared.b64 [%0], %1;" :: "r"(addr), "r"(cnt) : "memory")

#define MBARRIER_ARRIVE(addr) \
    asm volatile("mbarrier.arrive.shared.b64 _, [%0];" :: "r"(addr) : "memory")

#define MBARRIER_EXPECT_TX(addr, bytes) \
    asm volatile("mbarrier.arrive.expect_tx.shared.b64 _, [%0], %1;" \
                 :: "r"(addr), "r"(bytes) : "memory")

#define MBARRIER_WAIT_PARITY(addr, parity) do {                                   \
    uint32_t _mbar = (addr); uint32_t _par = (parity); uint32_t _done;            \
    asm volatile("{\n\t.reg .pred p;\n\t"                                         \
        "mbarrier.try_wait.parity.acquire.cta.shared::cta.b64 p, [%1], %2;\n\t"   \
        "selp.b32 %0, 1, 0, p;\n\t}"                                              \
        : "=r"(_done) : "r"(_mbar), "r"(_par) : "memory");                        \
    if (!_done) {                                                                 \
        asm volatile("{\n\t.reg .pred P1;\n\t"                                    \
            "WL_%=:\n\t"                                                          \
            "mbarrier.try_wait.parity.acquire.cta.shared::cta.b64 P1, [%0], %1, 0x989680;\n\t" \
            "@P1 bra.uni WD_%=;\n\t"                                              \
            "bra.uni WL_%=;\n\t"                                                  \
            "WD_%=:\n\t}" :: "r"(_mbar), "r"(_par) : "memory");                   \
    }                                                                             \
} while (0)

#define MBARRIER_WAIT_PARITY_RELAXED(addr, parity) do {                           \
    uint32_t _mbar = (addr); uint32_t _par = (parity); uint32_t _done;            \
    asm volatile("{\n\t.reg .pred p;\n\t"                                         \
        "mbarrier.try_wait.parity.relaxed.cta.shared::cta.b64 p, [%1], %2, 0x989680;\n\t" \
        "selp.b32 %0, 1, 0, p;\n\t}"                                              \
        : "=r"(_done) : "r"(_mbar), "r"(_par) : "memory");                        \
    if (!_done) {                                                                 \
        asm volatile("{\n\t.reg .pred P1;\n\t"                                    \
            "WL_%=:\n\t"                                                          \
            "mbarrier.try_wait.parity.relaxed.cta.shared::cta.b64 P1, [%0], %1, 0x989680;\n\t" \
            "@P1 bra.uni WD_%=;\n\t"                                              \
            "bra.uni WL_%=;\n\t"                                                  \
            "WD_%=:\n\t}" :: "r"(_mbar), "r"(_par) : "memory");                   \
    }                                                                             \
} while (0)

// Bulk copy with L2 evict_first policy (stream-once data: don't retain in L2).
__device__ __forceinline__ void tma_bulk_g2s_ef(uint32_t smem_dst, const void* gmem_src,
                                                uint32_t bytes, uint32_t mbar,
                                                uint64_t policy) {
    asm volatile(
        "cp.async.bulk.shared::cluster.global.mbarrier::complete_tx::bytes.L2::cache_hint "
        "[%0], [%1], %2, [%3], %4;"
        :: "r"(smem_dst), "l"(gmem_src), "r"(bytes), "r"(mbar), "l"(policy)
        : "memory");
}

__global__ __launch_bounds__(THREADS)
void l1pen_kernel(const float* __restrict__ pred,
                  const float* __restrict__ tgt,
                  const float* __restrict__ pen,
                  int nrows,
                  float* __restrict__ out)
{
    extern __shared__ float dynsm[];            // [STAGES][2][TILE_F]
    __shared__ alignas(16) unsigned long long mbars[2 * STAGES]; // full/empty pairs
    __shared__ float s_warp[CONS / 32];

    const int tid    = threadIdx.x;
    const int wid    = tid >> 5;
    const int nfull  = nrows / ROWS;            // full tiles (4096 for N=1M)
    const int ntiles = (nrows + ROWS - 1) / ROWS;
    const int stride = gridDim.x;

    const uint32_t mb0 = (uint32_t)__cvta_generic_to_shared(mbars);
    auto full_addr  = [&](int s) { return mb0 + (uint32_t)(2 * s) * 8u; };
    auto empty_addr = [&](int s) { return mb0 + (uint32_t)(2 * s + 1) * 8u; };

    if (tid == 0) {
        #pragma unroll
        for (int s = 0; s < STAGES; s++) {
            MBARRIER_INIT(full_addr(s), 1u);               // producer's expect_tx arrive
            MBARRIER_INIT(empty_addr(s), (uint32_t)CONS);  // all consumers arrive
        }
    }
    __syncthreads();

    float acc = 0.0f;

    if (wid == 4) {
        // -------- producer warp (lane 0 only) --------
        if ((tid & 31) == 0) {
            uint64_t policy;
            asm volatile("createpolicy.fractional.L2::evict_first.b64 %0, 1.0;"
                         : "=l"(policy));
            int s = 0, phase = 1;                // phase=1: first empty-wait passes
            for (int tile = blockIdx.x; tile < nfull; tile += stride) {
                MBARRIER_WAIT_PARITY_RELAXED(empty_addr(s), phase);
                MBARRIER_EXPECT_TX(full_addr(s), 2u * TILE_B);
                const uint32_t dst =
                    (uint32_t)__cvta_generic_to_shared(dynsm + s * STAGE_F);
                tma_bulk_g2s_ef(dst,          pred + (long)tile * TILE_F, TILE_B,
                                full_addr(s), policy);
                tma_bulk_g2s_ef(dst + TILE_B, tgt  + (long)tile * TILE_F, TILE_B,
                                full_addr(s), policy);
                if (++s == STAGES) { s = 0; phase ^= 1; }
            }
        }
    } else {
        // -------- consumer warps: 2 rows per thread per tile --------
        int s = 0, phase = 0;
        for (int tile = blockIdx.x; tile < ntiles; tile += stride) {
            if (tile < nfull) {
                MBARRIER_WAIT_PARITY(full_addr(s), phase);   // acquire: TMA data visible
                const float* base_p = dynsm + s * STAGE_F;
                #pragma unroll
                for (int r = 0; r < 2; r++) {
                    const float* __restrict__ pr = base_p + (tid + r * CONS) * C;
                    const float* __restrict__ tr = pr + TILE_F;
                    float l1 = 0.0f;
                    float pmax = pr[0], tmax = tr[0];
                    int   pidx = 0,     tidx = 0;
                    #pragma unroll
                    for (int c = 0; c < C; c++) {
                        float a = pr[c];
                        float b = tr[c];
                        l1 += fabsf(a - b);
                        if (a > pmax) { pmax = a; pidx = c; }  // strict > == jnp.argmax ties
                        if (b > tmax) { tmax = b; tidx = c; }
                    }
                    acc += l1 * __ldg(&pen[pidx * C + tidx]);
                }
                MBARRIER_ARRIVE(empty_addr(s));              // release: reads done
                if (++s == STAGES) { s = 0; phase ^= 1; }
            } else {
                // ragged last tile (dead for N=1M = 4096 full tiles)
                const int rows = nrows - nfull * ROWS;
                #pragma unroll
                for (int r = 0; r < 2; r++) {
                    const int row = tid + r * CONS;
                    if (row < rows) {
                        const long base = (long)(nfull * ROWS + row) * C;
                        float l1 = 0.0f;
                        float pmax = pred[base], tmax = tgt[base];
                        int   pidx = 0,          tidx = 0;
                        #pragma unroll
                        for (int c = 0; c < C; c++) {
                            float a = pred[base + c];
                            float b = tgt [base + c];
                            l1 += fabsf(a - b);
                            if (a > pmax) { pmax = a; pidx = c; }
                            if (b > tmax) { tmax = b; tidx = c; }
                        }
                        acc += l1 * __ldg(&pen[pidx * C + tidx]);
                    }
                }
            }
        }

        // warp reduce (consumer warps only)
        #pragma unroll
        for (int off = 16; off > 0; off >>= 1)
            acc += __shfl_down_sync(0xffffffffu, acc, off);
        if ((tid & 31) == 0)
            s_warp[wid] = acc;
    }

    __syncthreads();   // all 5 warps: consumers done writing s_warp

    if (tid == 0) {
        float s = 0.0f;
        #pragma unroll
        for (int w = 0; w < CONS / 32; w++)
            s += s_warp[w];

        atomicAdd(&g_acc, (double)s);
        __threadfence();
        unsigned done = atomicAdd(&g_count, 1u) + 1u;
        if (done == gridDim.x) {
            __threadfence();
            double v = atomicAdd(&g_acc, 0.0);
            *out = (float)(v / (double)nrows);
            g_acc = 0.0;              // self-reset for next graph replay
            __threadfence();
            g_count = 0u;
        }
    }
}

extern "C" void kernel_launch(void* const* d_in, const int* in_sizes, int n_in,
                              void* d_out, int out_size)
{
    int pen_i = -1;
    for (int i = 0; i < n_in; i++)
        if (in_sizes[i] == C * C) { pen_i = i; break; }
    int big[2], nb = 0;
    for (int i = 0; i < n_in && nb < 2; i++)
        if (i != pen_i) big[nb++] = i;

    const float* pred = (const float*)d_in[big[0]];
    const float* tgt  = (const float*)d_in[big[1]];
    const float* pen  = (const float*)d_in[pen_i];

    const int nrows = in_sizes[big[0]] / C;

    cudaFuncSetAttribute(l1pen_kernel,
                         cudaFuncAttributeMaxDynamicSharedMemorySize, SMEM_BYTES);

    l1pen_kernel<<<GRID, THREADS, SMEM_BYTES>>>(pred, tgt, pen, nrows,
                                                (float*)d_out);
}

// round 16
// speedup vs baseline: 1.0015x; 1.0015x over previous
#include <cuda_runtime.h>
#include <cstdint>

// L1LossWithPenalty — FINAL (session close): R11 champion, byte-for-byte.
// Warp-specialized TMA-bulk pipeline (1 producer warp + 4 consumer warps),
// 4-stage mbarrier ring, 128-row tiles, 2 blocks/SM, L2 evict_first.
// out = (1/N) * sum_i [ sum_c |pred[i,c]-tgt[i,c]| ] * penalty[argmax pred_i, argmax tgt_i]
// N = 1048576, C = 27.  226 MB streamed at ~5.6 TB/s sustained = 40.3us floor;
// this kernel measures ~41.1-41.3us = ~98% of the empirical HBM roofline.
//
// Session: 59.6us (3-kernel smem-staged) -> 47.1 (cp.async pipelined) ->
// 42.5 (warp-specialized TMA) -> 41.3 (+L2 evict_first). All other levers
// (pipeline depth, tile size, blocks/SM, dual-path, arrive granularity,
// penalty placement, 256-row/2-stage cell) isolated and measured neutral or
// regressive. DRAM is the only loaded resource (all compute pipes <25%).

#define C        27
#define ROWS     128                  // rows per tile (= consumer threads)
#define CONS     128                  // consumer threads (4 warps)
#define THREADS  160                  // + 1 producer warp
#define TILE_F   (ROWS * C)           // 3456 floats
#define TILE_B   (TILE_F * 4)         // 13824 bytes per array per tile
#define STAGE_F  (2 * TILE_F)
#define STAGES   4
#define SMEM_BYTES (STAGES * STAGE_F * 4)   // 110592 B
#define GRID     296

__device__ double   g_acc;
__device__ unsigned g_count;

// ---- mbarrier / TMA-bulk primitives ----
#define MBARRIER_INIT(addr, cnt) \
    asm volatile("mbarrier.init.shared.b64 [%0], %1;" :: "r"(addr), "r"(cnt) : "memory")

#define MBARRIER_ARRIVE(addr) \
    asm volatile("mbarrier.arrive.shared.b64 _, [%0];" :: "r"(addr) : "memory")

#define MBARRIER_EXPECT_TX(addr, bytes) \
    asm volatile("mbarrier.arrive.expect_tx.shared.b64 _, [%0], %1;" \
                 :: "r"(addr), "r"(bytes) : "memory")

#define MBARRIER_WAIT_PARITY(addr, parity) do {                                   \
    uint32_t _mbar = (addr); uint32_t _par = (parity); uint32_t _done;            \
    asm volatile("{\n\t.reg .pred p;\n\t"                                         \
        "mbarrier.try_wait.parity.acquire.cta.shared::cta.b64 p, [%1], %2;\n\t"   \
        "selp.b32 %0, 1, 0, p;\n\t}"                                              \
        : "=r"(_done) : "r"(_mbar), "r"(_par) : "memory");                        \
    if (!_done) {                                                                 \
        asm volatile("{\n\t.reg .pred P1;\n\t"                                    \
            "WL_%=:\n\t"                                                          \
            "mbarrier.try_wait.parity.acquire.cta.shared::cta.b64 P1, [%0], %1, 0x989680;\n\t" \
            "@P1 bra.uni WD_%=;\n\t"                                              \
            "bra.uni WL_%=;\n\t"                                                  \
            "WD_%=:\n\t}" :: "r"(_mbar), "r"(_par) : "memory");                   \
    }                                                                             \
} while (0)

#define MBARRIER_WAIT_PARITY_RELAXED(addr, parity) do {                           \
    uint32_t _mbar = (addr); uint32_t _par = (parity); uint32_t _done;            \
    asm volatile("{\n\t.reg .pred p;\n\t"                                         \
        "mbarrier.try_wait.parity.relaxed.cta.shared::cta.b64 p, [%1], %2, 0x989680;\n\t" \
        "selp.b32 %0, 1, 0, p;\n\t}"                                              \
        : "=r"(_done) : "r"(_mbar), "r"(_par) : "memory");                        \
    if (!_done) {                                                                 \
        asm volatile("{\n\t.reg .pred P1;\n\t"                                    \
            "WL_%=:\n\t"                                                          \
            "mbarrier.try_wait.parity.relaxed.cta.shared::cta.b64 P1, [%0], %1, 0x989680;\n\t" \
            "@P1 bra.uni WD_%=;\n\t"                                              \
            "bra.uni WL_%=;\n\t"                                                  \
            "WD_%=:\n\t}" :: "r"(_mbar), "r"(_par) : "memory");                   \
    }                                                                             \
} while (0)

// Bulk copy with L2 evict_first policy (stream-once data: don't retain in L2).
__device__ __forceinline__ void tma_bulk_g2s_ef(uint32_t smem_dst, const void* gmem_src,
                                                uint32_t bytes, uint32_t mbar,
                                                uint64_t policy) {
    asm volatile(
        "cp.async.bulk.shared::cluster.global.mbarrier::complete_tx::bytes.L2::cache_hint "
        "[%0], [%1], %2, [%3], %4;"
        :: "r"(smem_dst), "l"(gmem_src), "r"(bytes), "r"(mbar), "l"(policy)
        : "memory");
}

__global__ __launch_bounds__(THREADS)
void l1pen_kernel(const float* __restrict__ pred,
                  const float* __restrict__ tgt,
                  const float* __restrict__ pen,
                  int nrows,
                  float* __restrict__ out)
{
    extern __shared__ float dynsm[];            // [STAGES][2][TILE_F]
    __shared__ alignas(16) unsigned long long mbars[2 * STAGES]; // full/empty pairs
    __shared__ float s_warp[CONS / 32];

    const int tid    = threadIdx.x;
    const int wid    = tid >> 5;
    const int nfull  = nrows / ROWS;            // full tiles (8192 for N=1M)
    const int ntiles = (nrows + ROWS - 1) / ROWS;
    const int stride = gridDim.x;

    const uint32_t mb0 = (uint32_t)__cvta_generic_to_shared(mbars);
    auto full_addr  = [&](int s) { return mb0 + (uint32_t)(2 * s) * 8u; };
    auto empty_addr = [&](int s) { return mb0 + (uint32_t)(2 * s + 1) * 8u; };

    if (tid == 0) {
        #pragma unroll
        for (int s = 0; s < STAGES; s++) {
            MBARRIER_INIT(full_addr(s), 1u);               // producer's expect_tx arrive
            MBARRIER_INIT(empty_addr(s), (uint32_t)CONS);  // all consumers arrive
        }
    }
    __syncthreads();

    float acc = 0.0f;

    if (wid == 4) {
        // -------- producer warp (lane 0 only) --------
        if ((tid & 31) == 0) {
            uint64_t policy;
            asm volatile("createpolicy.fractional.L2::evict_first.b64 %0, 1.0;"
                         : "=l"(policy));
            int s = 0, phase = 1;                // phase=1: first empty-wait passes
            for (int tile = blockIdx.x; tile < nfull; tile += stride) {
                MBARRIER_WAIT_PARITY_RELAXED(empty_addr(s), phase);
                MBARRIER_EXPECT_TX(full_addr(s), 2u * TILE_B);
                const uint32_t dst =
                    (uint32_t)__cvta_generic_to_shared(dynsm + s * STAGE_F);
                tma_bulk_g2s_ef(dst,          pred + (long)tile * TILE_F, TILE_B,
                                full_addr(s), policy);
                tma_bulk_g2s_ef(dst + TILE_B, tgt  + (long)tile * TILE_F, TILE_B,
                                full_addr(s), policy);
                if (++s == STAGES) { s = 0; phase ^= 1; }
            }
        }
    } else {
        // -------- consumer warps (128 threads, 1 row each per tile) --------
        int s = 0, phase = 0;
        for (int tile = blockIdx.x; tile < ntiles; tile += stride) {
            if (tile < nfull) {
                MBARRIER_WAIT_PARITY(full_addr(s), phase);   // acquire: TMA data visible
                const float* __restrict__ pr = dynsm + s * STAGE_F + tid * C;
                const float* __restrict__ tr = pr + TILE_F;
                float l1 = 0.0f;
                float pmax = pr[0], tmax = tr[0];
                int   pidx = 0,     tidx = 0;
                #pragma unroll
                for (int c = 0; c < C; c++) {
                    float a = pr[c];
                    float b = tr[c];
                    l1 += fabsf(a - b);
                    if (a > pmax) { pmax = a; pidx = c; }   // strict > == jnp.argmax ties
                    if (b > tmax) { tmax = b; tidx = c; }
                }
                acc += l1 * __ldg(&pen[pidx * C + tidx]);
                MBARRIER_ARRIVE(empty_addr(s));              // release: reads done
                if (++s == STAGES) { s = 0; phase ^= 1; }
            } else {
                // ragged last tile (dead for N=1M): direct global reads
                const int rows = nrows - nfull * ROWS;
                if (tid < rows) {
                    const long base = (long)(nfull * ROWS + tid) * C;
                    float l1 = 0.0f;
                    float pmax = pred[base], tmax = tgt[base];
                    int   pidx = 0,          tidx = 0;
                    #pragma unroll
                    for (int c = 0; c < C; c++) {
                        float a = pred[base + c];
                        float b = tgt [base + c];
                        l1 += fabsf(a - b);
                        if (a > pmax) { pmax = a; pidx = c; }
                        if (b > tmax) { tmax = b; tidx = c; }
                    }
                    acc += l1 * __ldg(&pen[pidx * C + tidx]);
                }
            }
        }

        // warp reduce (consumer warps only)
        #pragma unroll
        for (int off = 16; off > 0; off >>= 1)
            acc += __shfl_down_sync(0xffffffffu, acc, off);
        if ((tid & 31) == 0)
            s_warp[wid] = acc;
    }

    __syncthreads();   // all 5 warps: consumers done writing s_warp

    if (tid == 0) {
        float s = 0.0f;
        #pragma unroll
        for (int w = 0; w < CONS / 32; w++)
            s += s_warp[w];

        atomicAdd(&g_acc, (double)s);
        __threadfence();
        unsigned done = atomicAdd(&g_count, 1u) + 1u;
        if (done == gridDim.x) {
            __threadfence();
            double v = atomicAdd(&g_acc, 0.0);
            *out = (float)(v / (double)nrows);
            g_acc = 0.0;              // self-reset for next graph replay
            __threadfence();
            g_count = 0u;
        }
    }
}

extern "C" void kernel_launch(void* const* d_in, const int* in_sizes, int n_in,
                              void* d_out, int out_size)
{
    int pen_i = -1;
    for (int i = 0; i < n_in; i++)
        if (in_sizes[i] == C * C) { pen_i = i; break; }
    int big[2], nb = 0;
    for (int i = 0; i < n_in && nb < 2; i++)
        if (i != pen_i) big[nb++] = i;

    const float* pred = (const float*)d_in[big[0]];
    const float* tgt  = (const float*)d_in[big[1]];
    const float* pen  = (const float*)d_in[pen_i];

    const int nrows = in_sizes[big[0]] / C;

    cudaFuncSetAttribute(l1pen_kernel,
                         cudaFuncAttributeMaxDynamicSharedMemorySize, SMEM_BYTES);

    l1pen_kernel<<<GRID, THREADS, SMEM_BYTES>>>(pred, tgt, pen, nrows,
                                                (float*)d_out);
}